// round 4
// baseline (speedup 1.0000x reference)
#include <cuda_runtime.h>
#include <math.h>

// Problem constants
#define T_STEPS 1024
#define B_SZ    64
#define H_SZ    2048
#define G3H     6144

// Kernel config
#define NCTA    128          // persistent CTAs, 1 per SM (<=148)
#define NTH     128          // threads per CTA
#define GPC     16           // gates per CTA  (2048/128)
#define M_ROWS  48           // weight rows per CTA (3 * GPC)
#define KC      32           // k-chunk
#define NCHUNK  (H_SZ / KC)  // 64

typedef unsigned long long ull;

// Persistent device state (allowed: __device__ globals, no allocation)
__device__ __align__(16) float g_h[2][H_SZ * B_SZ];  // k-major: h[k*B + b], double buffered
__device__ unsigned g_count  = 0;
__device__ unsigned g_release = 0;

// ---- f32x2 helpers (FFMA2 path: rt_SMSP=1 instr per 2 MACs) ----
__device__ __forceinline__ ull pack2(float x, float y) {
    ull r; asm("mov.b64 %0, {%1,%2};" : "=l"(r) : "f"(x), "f"(y)); return r;
}
__device__ __forceinline__ void unpack2(ull v, float &x, float &y) {
    asm("mov.b64 {%0,%1}, %2;" : "=f"(x), "=f"(y) : "l"(v));
}
__device__ __forceinline__ ull ffma2(ull a, ull b, ull c) {
    ull d; asm("fma.rn.f32x2 %0, %1, %2, %3;" : "=l"(d) : "l"(a), "l"(b), "l"(c)); return d;
}

// Transpose init_hidden [B,H] (row-major) -> g_h[0] as [H][B]
__global__ void gru_init(const float* __restrict__ h0) {
    int i = blockIdx.x * blockDim.x + threadIdx.x;
    if (i < B_SZ * H_SZ) {
        int b = i / H_SZ;
        int g = i - b * H_SZ;
        g_h[0][g * B_SZ + b] = h0[i];
    }
}

__global__ void __launch_bounds__(NTH, 1)
gru_main(const float* __restrict__ inp,     // [T,B,3]
         const float* __restrict__ wih,     // [3H,3]
         const float* __restrict__ whh,     // [3H,H]
         const float* __restrict__ bias,    // [3H]
         const float* __restrict__ bias_n,  // [H]
         float* __restrict__ out)           // [T,B]
{
    __shared__ __align__(16) float a_s[2][KC][M_ROWS + 2];   // +2 pad: keeps 8B align, low conflicts
    __shared__ __align__(16) float h_s[2][KC][B_SZ];
    __shared__ float dot_s[M_ROWS][B_SZ + 1];
    __shared__ float wih_s[M_ROWS][3];
    __shared__ float bias_s[M_ROWS];
    __shared__ float biasn_s[GPC];
    __shared__ __align__(8) float inp_s[B_SZ * 3];

    const int tid  = threadIdx.x;
    const int cta  = blockIdx.x;
    const int g0   = cta * GPC;
    const int lane = tid & 31;
    const int warp = tid >> 5;
    const int ct   = tid & 15;       // 16 col-threads
    const int rt   = tid >> 4;       // 8 row-threads
    const int r0   = rt * 6;         // 6 rows per thread
    const int c0   = ct * 4;         // 4 cols per thread

    // Launch-relative barrier phase base (graph-replay safe; read before any arrival)
    unsigned rel_base = 0;
    if (tid == 0) rel_base = atomicAdd(&g_release, 0u);

    // Persistent per-CTA parameters (loaded once, live in smem for all 1024 steps)
    if (tid < M_ROWS) {
        int grow = (tid >> 4) * H_SZ + g0 + (tid & 15);
        wih_s[tid][0] = wih[grow * 3 + 0];
        wih_s[tid][1] = wih[grow * 3 + 1];
        wih_s[tid][2] = wih[grow * 3 + 2];
        bias_s[tid]   = bias[grow];
    }
    if (tid < GPC) biasn_s[tid] = bias_n[g0 + tid];
    __syncthreads();

    float  pa[12];
    float4 ph[4];

    auto ldA = [&](int c) {                      // 12 LDG.32 per thread (coalesced per warp)
        int k0 = c * KC;
        #pragma unroll
        for (int i = 0; i < 12; i++) {
            int r    = warp + i * 4;             // rows 0..47, each exactly once
            int grow = (r >> 4) * H_SZ + g0 + (r & 15);
            pa[i] = whh[grow * H_SZ + k0 + lane];
        }
    };
    auto ldH = [&](int c, const float* hcur) {   // 4 LDG.128, fully coalesced
        const float4* hsrc = (const float4*)(hcur + c * KC * B_SZ);
        #pragma unroll
        for (int j = 0; j < 4; j++) ph[j] = hsrc[tid + j * NTH];
    };
    auto stAB = [&](int buf) {
        #pragma unroll
        for (int i = 0; i < 12; i++) {
            int r = warp + i * 4;
            a_s[buf][lane][r] = pa[i];           // k-major transpose in smem
        }
        float4* hdst = (float4*)&h_s[buf][0][0];
        #pragma unroll
        for (int j = 0; j < 4; j++) hdst[tid + j * NTH] = ph[j];
    };

    for (int t = 0; t < T_STEPS; t++) {
        const float* hcur = g_h[t & 1];
        float*       hnxt = g_h[(t + 1) & 1];

        ull acc[3][4];
        #pragma unroll
        for (int i = 0; i < 3; i++)
            #pragma unroll
            for (int j = 0; j < 4; j++) acc[i][j] = 0ull;

        // Prologue: stage chunk 0
        ldA(0); ldH(0, hcur); stAB(0);
        __syncthreads();

        for (int c = 0; c < NCHUNK; c++) {
            const int buf = c & 1;
            // Prefetch next chunk into registers (LDG latency hidden by compute below)
            if (c + 1 < NCHUNK) { ldA(c + 1); ldH(c + 1, hcur); }

            #pragma unroll
            for (int k = 0; k < KC; k++) {
                ull a01 = *(const ull*)&a_s[buf][k][r0];       // row pair (r0,r0+1) packed
                ull a23 = *(const ull*)&a_s[buf][k][r0 + 2];
                ull a45 = *(const ull*)&a_s[buf][k][r0 + 4];
                float4 h4 = *(const float4*)&h_s[buf][k][c0];
                ull hh0 = pack2(h4.x, h4.x);
                ull hh1 = pack2(h4.y, h4.y);
                ull hh2 = pack2(h4.z, h4.z);
                ull hh3 = pack2(h4.w, h4.w);
                acc[0][0] = ffma2(a01, hh0, acc[0][0]);
                acc[0][1] = ffma2(a01, hh1, acc[0][1]);
                acc[0][2] = ffma2(a01, hh2, acc[0][2]);
                acc[0][3] = ffma2(a01, hh3, acc[0][3]);
                acc[1][0] = ffma2(a23, hh0, acc[1][0]);
                acc[1][1] = ffma2(a23, hh1, acc[1][1]);
                acc[1][2] = ffma2(a23, hh2, acc[1][2]);
                acc[1][3] = ffma2(a23, hh3, acc[1][3]);
                acc[2][0] = ffma2(a45, hh0, acc[2][0]);
                acc[2][1] = ffma2(a45, hh1, acc[2][1]);
                acc[2][2] = ffma2(a45, hh2, acc[2][2]);
                acc[2][3] = ffma2(a45, hh3, acc[2][3]);
            }

            if (c + 1 < NCHUNK) stAB(buf ^ 1);   // data arrived during compute
            __syncthreads();
        }

        // Scatter dot products to smem for the gate phase
        #pragma unroll
        for (int rp = 0; rp < 3; rp++) {
            #pragma unroll
            for (int cc = 0; cc < 4; cc++) {
                float lo, hi; unpack2(acc[rp][cc], lo, hi);
                dot_s[r0 + 2 * rp][c0 + cc]     = lo;
                dot_s[r0 + 2 * rp + 1][c0 + cc] = hi;
            }
        }
        if (tid < 96)
            *(float2*)&inp_s[tid * 2] = *(const float2*)&inp[t * (B_SZ * 3) + tid * 2];
        __syncthreads();

        // Gate epilogue: 16 gates x 64 batches = 1024 tasks
        #pragma unroll
        for (int it = 0; it < 8; it++) {
            int task = it * NTH + tid;
            int b = task & 63;
            int g = task >> 6;
            float dr = dot_s[g][b];
            float dz = dot_s[GPC + g][b];
            float dn = dot_s[2 * GPC + g][b];
            float x0 = inp_s[b * 3 + 0], x1 = inp_s[b * 3 + 1], x2 = inp_s[b * 3 + 2];
            float igr = bias_s[g]           + x0 * wih_s[g][0]           + x1 * wih_s[g][1]           + x2 * wih_s[g][2];
            float igz = bias_s[GPC + g]     + x0 * wih_s[GPC + g][0]     + x1 * wih_s[GPC + g][1]     + x2 * wih_s[GPC + g][2];
            float ign = bias_s[2 * GPC + g] + x0 * wih_s[2 * GPC + g][0] + x1 * wih_s[2 * GPC + g][1] + x2 * wih_s[2 * GPC + g][2];
            float rg = 1.0f / (1.0f + expf(-(igr + dr)));
            float zg = 1.0f / (1.0f + expf(-(igz + dz)));
            float nn = tanhf(ign + rg * (dn + biasn_s[g]));
            float hold = hcur[(g0 + g) * B_SZ + b];
            float hnew = nn + zg * (hold - nn);
            hnxt[(g0 + g) * B_SZ + b] = hnew;
            if (g0 + g == 0) out[t * B_SZ + b] = hnew;
        }

        // ---- grid-wide barrier (monotonic release counter, launch-relative base) ----
        __threadfence();          // every thread: publish its h stores (cumulative fence chain)
        __syncthreads();
        if (tid == 0) {
            unsigned prev = atomicAdd(&g_count, 1u);
            if (prev == NCTA - 1) {
                atomicExch(&g_count, 0u);        // reset before release; no concurrent adders
                __threadfence();
                atomicAdd(&g_release, 1u);
            } else {
                unsigned target = rel_base + (unsigned)t + 1u;
                while (atomicAdd(&g_release, 0u) < target) __nanosleep(64);
            }
            __threadfence();      // acquire side
        }
        __syncthreads();
    }
}

extern "C" void kernel_launch(void* const* d_in, const int* in_sizes, int n_in,
                              void* d_out, int out_size) {
    const float* inp    = (const float*)d_in[0];  // [T,B,3]
    const float* h0     = (const float*)d_in[1];  // [B,H]
    const float* wih    = (const float*)d_in[2];  // [3H,3]
    const float* whh    = (const float*)d_in[3];  // [3H,H]
    const float* bias   = (const float*)d_in[4];  // [3H]
    const float* bn     = (const float*)d_in[5];  // [H]
    float* out = (float*)d_out;                   // [T,B] fp32

    gru_init<<<(B_SZ * H_SZ + 255) / 256, 256>>>(h0);
    gru_main<<<NCTA, NTH>>>(inp, wih, whh, bias, bn, out);
}

// round 6
// speedup vs baseline: 1.4693x; 1.4693x over previous
#include <cuda_runtime.h>
#include <cuda_bf16.h>
#include <cstdint>
#include <math.h>

// ---------------- problem constants ----------------
#define T_STEPS 1024
#define B_SZ    64
#define H_SZ    2048
#define G3H     6144

// ---------------- kernel config ----------------
#define NCTA   128           // persistent CTAs; CTA tile M = 48 (48*128 = 6144)
#define NTH    192           // 6 warps: 3 (m) x 2 (n)
#define TILE_M 48
#define KC     128           // k elems per chunk
#define NCH    16            // chunks covering K=2048
#define ROWB   272           // padded SMEM/gmem-image row stride (256B data + 16B pad)
#define WCH_B  (TILE_M * ROWB)   // 13056 bytes per W chunk (one phase)
#define HCH_B  (B_SZ * ROWB)     // 17408 bytes per h chunk (one phase)
#define WPAIR  (2 * WCH_B)       // hi+lo contiguous = 26112
#define HPAIR  (2 * HCH_B)       // hi+lo contiguous = 34816
#define SM_H_OFF WPAIR
#define BUF_B  61440             // per-buffer stride >= WPAIR+HPAIR (60928)
#define SMEM_DYN (2 * BUF_B + 256)

// ---------------- persistent device state ----------------
__device__ uint4 g_wA[(size_t)NCTA * NCH * WPAIR / 16]; // [m][chunk][phase][48][272]
__device__ uint4 g_hb[(size_t)NCH * HPAIR / 16];        // [chunk][phase][64][272]
__device__ float g_D[G3H * B_SZ];                       // GEMM result [6144][64]
__device__ unsigned g_count = 0, g_release = 0;

// ---------------- helpers ----------------
__device__ __forceinline__ uint32_t smem_u32(const void* p) {
    uint32_t a;
    asm("{ .reg .u64 t; cvta.to.shared.u64 t, %1; cvt.u32.u64 %0, t; }" : "=r"(a) : "l"(p));
    return a;
}
__device__ __forceinline__ void cp16(uint32_t dst, const void* src) {
    asm volatile("cp.async.cg.shared.global [%0], [%1], 16;" :: "r"(dst), "l"(src) : "memory");
}
__device__ __forceinline__ void cp_commit() { asm volatile("cp.async.commit_group;" ::: "memory"); }
__device__ __forceinline__ void cp_wait1()  { asm volatile("cp.async.wait_group 1;" ::: "memory"); }
__device__ __forceinline__ void cp_wait0()  { asm volatile("cp.async.wait_group 0;" ::: "memory"); }

#define LDSM4(r0, r1, r2, r3, addr) \
    asm volatile("ldmatrix.sync.aligned.m8n8.x4.shared.b16 {%0,%1,%2,%3}, [%4];" \
                 : "=r"(r0), "=r"(r1), "=r"(r2), "=r"(r3) : "r"(addr))

#define MMA(d, a0, a1, a2, a3, b0, b1) \
    asm volatile("mma.sync.aligned.m16n8k16.row.col.f32.bf16.bf16.f32 " \
                 "{%0,%1,%2,%3}, {%4,%5,%6,%7}, {%8,%9}, {%0,%1,%2,%3};" \
                 : "+f"((d)[0]), "+f"((d)[1]), "+f"((d)[2]), "+f"((d)[3]) \
                 : "r"(a0), "r"(a1), "r"(a2), "r"(a3), "r"(b0), "r"(b1))

// ---------------- init: split W/h into bf16 hi/lo padded chunk images ----------------
__global__ void w_init(const float* __restrict__ whh) {
    int id = blockIdx.x * 256 + threadIdx.x;   // 128*16*2*48*16 = 3,145,728 tasks
    int kb = id & 15;  id >>= 4;
    int r  = id % 48;  id /= 48;
    int p  = id & 1;   id >>= 1;
    int c  = id & 15;  id >>= 4;
    int m  = id;                                // 0..127
    int row = m * TILE_M + r;
    int k0  = c * KC + kb * 8;
    const float4* src = (const float4*)(whh + (size_t)row * H_SZ + k0);
    float4 f0 = src[0], f1 = src[1];
    float v[8] = {f0.x, f0.y, f0.z, f0.w, f1.x, f1.y, f1.z, f1.w};
    unsigned short o[8];
    #pragma unroll
    for (int j = 0; j < 8; j++) {
        __nv_bfloat16 hi = __float2bfloat16_rn(v[j]);
        __nv_bfloat16 val = (p == 0) ? hi : __float2bfloat16_rn(v[j] - __bfloat162float(hi));
        o[j] = *(unsigned short*)&val;
    }
    size_t byte = ((size_t)(m * NCH + c) * 2 + p) * WCH_B + (size_t)r * ROWB + kb * 16;
    *(uint4*)((char*)g_wA + byte) = *(uint4*)o;
}

__global__ void h_init(const float* __restrict__ h0) {
    int id = blockIdx.x * 256 + threadIdx.x;   // 16*2*64*16 = 32768 tasks
    int kb = id & 15;  id >>= 4;
    int b  = id & 63;  id >>= 6;
    int p  = id & 1;   id >>= 1;
    int c  = id;                                // 0..15
    int k0 = c * KC + kb * 8;
    const float4* src = (const float4*)(h0 + (size_t)b * H_SZ + k0);
    float4 f0 = src[0], f1 = src[1];
    float v[8] = {f0.x, f0.y, f0.z, f0.w, f1.x, f1.y, f1.z, f1.w};
    unsigned short o[8];
    #pragma unroll
    for (int j = 0; j < 8; j++) {
        __nv_bfloat16 hi = __float2bfloat16_rn(v[j]);
        __nv_bfloat16 val = (p == 0) ? hi : __float2bfloat16_rn(v[j] - __bfloat162float(hi));
        o[j] = *(unsigned short*)&val;
    }
    size_t byte = ((size_t)c * 2 + p) * HCH_B + (size_t)b * ROWB + kb * 16;
    *(uint4*)((char*)g_hb + byte) = *(uint4*)o;
}

// ---------------- main persistent kernel ----------------
__global__ void __launch_bounds__(NTH, 1)
gru_main(const float* __restrict__ inp,     // [T,B,3]
         const float* __restrict__ wih,     // [3H,3]
         const float* __restrict__ bias,    // [3H]
         const float* __restrict__ bias_n,  // [H]
         float* __restrict__ out)           // [T,B]
{
    extern __shared__ unsigned char sm[];

    const int tid = threadIdx.x;
    const int wid = tid >> 5;        // 0..5
    const int lid = tid & 31;
    const int mw  = wid >> 1;        // 0..2  (m warp tile)
    const int nw  = wid & 1;         // 0..1  (n warp tile)
    const int m   = blockIdx.x;

    const uint32_t smb = smem_u32(sm);

    // ldmatrix per-lane byte offsets (within a buffer)
    const uint32_t aOff = (uint32_t)(mw * 16 + (lid & 15)) * ROWB + (uint32_t)(lid >> 4) * 16;
    const uint32_t bOff = SM_H_OFF
                        + (uint32_t)(nw * 32 + ((lid >> 4) & 1) * 8 + (lid & 7)) * ROWB
                        + (uint32_t)((lid >> 3) & 1) * 16;

    unsigned rel_base = 0;
    if (tid == 0) rel_base = atomicAdd(&g_release, 0u);
    __syncthreads();

    const char* wsrc_base = (const char*)g_wA + (size_t)m * NCH * WPAIR;
    const char* hsrc_base = (const char*)g_hb;

    auto stage = [&](int c, int buf) {
        const char* sW = wsrc_base + (size_t)c * WPAIR;
        const char* sH = hsrc_base + (size_t)c * HPAIR;
        uint32_t dW = smb + buf * BUF_B;
        uint32_t dH = dW + SM_H_OFF;
        for (int i = tid; i < WPAIR / 16; i += NTH) cp16(dW + i * 16, sW + i * 16);
        for (int i = tid; i < HPAIR / 16; i += NTH) cp16(dH + i * 16, sH + i * 16);
    };

    const int u0 = m * (H_SZ / NCTA);   // 16 hidden units per CTA for gate phase

    for (int t = 0; t < T_STEPS; t++) {
        float acc[4][4];
        #pragma unroll
        for (int f = 0; f < 4; f++)
            #pragma unroll
            for (int j = 0; j < 4; j++) acc[f][j] = 0.0f;

        // ---------------- GEMM: D = Whi*hhi + Whi*hlo + Wlo*hhi ----------------
        stage(0, 0); cp_commit();
        for (int c = 0; c < NCH; c++) {
            const int buf = c & 1;
            if (c + 1 < NCH) { stage(c + 1, buf ^ 1); cp_commit(); cp_wait1(); }
            else             { cp_wait0(); }
            __syncthreads();

            const uint32_t base = smb + buf * BUF_B;
            #pragma unroll
            for (int ks = 0; ks < 8; ks++) {
                uint32_t ah0, ah1, ah2, ah3, al0, al1, al2, al3;
                uint32_t aAddr = base + aOff + ks * 32;
                LDSM4(ah0, ah1, ah2, ah3, aAddr);            // Whi m16k16
                LDSM4(al0, al1, al2, al3, aAddr + WCH_B);    // Wlo m16k16

                uint32_t bAddr = base + bOff + ks * 32;
                uint32_t h0r, h1r, h2r, h3r, h4r, h5r, h6r, h7r;
                LDSM4(h0r, h1r, h2r, h3r, bAddr);                     // hhi n0:16
                LDSM4(h4r, h5r, h6r, h7r, bAddr + 16 * ROWB);         // hhi n16:32
                uint32_t l0r, l1r, l2r, l3r, l4r, l5r, l6r, l7r;
                LDSM4(l0r, l1r, l2r, l3r, bAddr + HCH_B);             // hlo n0:16
                LDSM4(l4r, l5r, l6r, l7r, bAddr + HCH_B + 16 * ROWB); // hlo n16:32

                MMA(acc[0], ah0, ah1, ah2, ah3, h0r, h1r);
                MMA(acc[1], ah0, ah1, ah2, ah3, h2r, h3r);
                MMA(acc[2], ah0, ah1, ah2, ah3, h4r, h5r);
                MMA(acc[3], ah0, ah1, ah2, ah3, h6r, h7r);

                MMA(acc[0], ah0, ah1, ah2, ah3, l0r, l1r);
                MMA(acc[1], ah0, ah1, ah2, ah3, l2r, l3r);
                MMA(acc[2], ah0, ah1, ah2, ah3, l4r, l5r);
                MMA(acc[3], ah0, ah1, ah2, ah3, l6r, l7r);

                MMA(acc[0], al0, al1, al2, al3, h0r, h1r);
                MMA(acc[1], al0, al1, al2, al3, h2r, h3r);
                MMA(acc[2], al0, al1, al2, al3, h4r, h5r);
                MMA(acc[3], al0, al1, al2, al3, h6r, h7r);
            }
            __syncthreads();
        }

        // ---------------- epilogue: acc -> g_D ----------------
        {
            int rbase = m * TILE_M + mw * 16 + (lid >> 2);
            int cb    = nw * 32 + (lid & 3) * 2;
            #pragma unroll
            for (int f = 0; f < 4; f++) {
                float2* p0 = (float2*)&g_D[(size_t)rbase * B_SZ + cb + f * 8];
                float2* p1 = (float2*)&g_D[(size_t)(rbase + 8) * B_SZ + cb + f * 8];
                *p0 = make_float2(acc[f][0], acc[f][1]);
                *p1 = make_float2(acc[f][2], acc[f][3]);
            }
        }

        // ---- grid barrier #1 (D ready) ----
        __threadfence();
        __syncthreads();
        if (tid == 0) {
            unsigned prev = atomicAdd(&g_count, 1u);
            if (prev == NCTA - 1) { atomicExch(&g_count, 0u); __threadfence(); atomicAdd(&g_release, 1u); }
            else { unsigned tgt = rel_base + 2u * (unsigned)t + 1u;
                   while (atomicAdd(&g_release, 0u) < tgt) __nanosleep(32); }
            __threadfence();
        }
        __syncthreads();

        // ---------------- gate phase: 16 units x 64 batches ----------------
        const float* xt = inp + (size_t)t * (B_SZ * 3);
        for (int idx = tid; idx < 16 * B_SZ; idx += NTH) {
            int u = u0 + (idx >> 6);
            int b = idx & 63;
            float dr = __ldcg(&g_D[(size_t)u * B_SZ + b]);
            float dz = __ldcg(&g_D[(size_t)(H_SZ + u) * B_SZ + b]);
            float dn = __ldcg(&g_D[(size_t)(2 * H_SZ + u) * B_SZ + b]);
            float x0 = xt[b * 3 + 0], x1 = xt[b * 3 + 1], x2 = xt[b * 3 + 2];
            float igr = bias[u]            + x0 * wih[u * 3]              + x1 * wih[u * 3 + 1]              + x2 * wih[u * 3 + 2];
            float igz = bias[H_SZ + u]     + x0 * wih[(H_SZ + u) * 3]     + x1 * wih[(H_SZ + u) * 3 + 1]     + x2 * wih[(H_SZ + u) * 3 + 2];
            float ign = bias[2 * H_SZ + u] + x0 * wih[(2 * H_SZ + u) * 3] + x1 * wih[(2 * H_SZ + u) * 3 + 1] + x2 * wih[(2 * H_SZ + u) * 3 + 2];

            int ch = u >> 7;
            char* hb = (char*)g_hb + (size_t)ch * HPAIR + (size_t)b * ROWB + (u & 127) * 2;
            __nv_bfloat16* phi = (__nv_bfloat16*)hb;
            __nv_bfloat16* plo = (__nv_bfloat16*)(hb + HCH_B);
            float hold = __bfloat162float(*phi) + __bfloat162float(*plo);

            float rg = 1.0f / (1.0f + expf(-(igr + dr)));
            float zg = 1.0f / (1.0f + expf(-(igz + dz)));
            float nn = tanhf(ign + rg * (dn + bias_n[u]));
            float hn = nn + zg * (hold - nn);

            __nv_bfloat16 nhi = __float2bfloat16_rn(hn);
            __nv_bfloat16 nlo = __float2bfloat16_rn(hn - __bfloat162float(nhi));
            *phi = nhi;
            *plo = nlo;
            if (u == 0) out[(size_t)t * B_SZ + b] = hn;
        }

        // ---- grid barrier #2 (h ready) ----
        __threadfence();
        __syncthreads();
        if (tid == 0) {
            unsigned prev = atomicAdd(&g_count, 1u);
            if (prev == NCTA - 1) { atomicExch(&g_count, 0u); __threadfence(); atomicAdd(&g_release, 1u); }
            else { unsigned tgt = rel_base + 2u * (unsigned)t + 2u;
                   while (atomicAdd(&g_release, 0u) < tgt) __nanosleep(32); }
            __threadfence();
        }
        __syncthreads();
    }
}

extern "C" void kernel_launch(void* const* d_in, const int* in_sizes, int n_in,
                              void* d_out, int out_size) {
    const float* inp  = (const float*)d_in[0];  // [T,B,3]
    const float* h0   = (const float*)d_in[1];  // [B,H]
    const float* wih  = (const float*)d_in[2];  // [3H,3]
    const float* whh  = (const float*)d_in[3];  // [3H,H]
    const float* bias = (const float*)d_in[4];  // [3H]
    const float* bn   = (const float*)d_in[5];  // [H]
    float* out = (float*)d_out;                 // [T,B]

    cudaFuncSetAttribute(gru_main, cudaFuncAttributeMaxDynamicSharedMemorySize, SMEM_DYN);

    w_init<<<12288, 256>>>(whh);   // 3,145,728 tasks
    h_init<<<128, 256>>>(h0);      // 32,768 tasks
    gru_main<<<NCTA, NTH, SMEM_DYN>>>(inp, wih, bias, bn, out);
}

// round 7
// speedup vs baseline: 2.5514x; 1.7365x over previous
#include <cuda_runtime.h>
#include <cuda_bf16.h>
#include <cstdint>
#include <math.h>

// ---------------- problem constants ----------------
#define T_STEPS 1024
#define B_SZ    64
#define H_SZ    2048
#define G3H     6144

// ---------------- kernel config ----------------
#define NCTA   128          // persistent CTAs, TILE_M = 48 rows each
#define NTH    384          // 12 warps = 3 (m16) x 4 (n16)
#define MT_TOT 384          // total m16 tiles (6144/16)
#define KT_N   128          // k16 tiles (2048/16)

// ---------------- persistent device state (fragment-ordered images) ----------------
// W: [phase(hi/lo)][mt 384][kt 128][lane 32] x 16B  (A frag a0..a3 per lane)
__device__ uint4 g_w[(size_t)2 * MT_TOT * KT_N * 32];
// h: [phase][nt 8][kt 128][lane 32] x 8B  (B frag b0,b1 per lane)
__device__ uint2 g_h[(size_t)2 * 8 * KT_N * 32];
__device__ float g_hf[H_SZ * B_SZ];        // exact fp32 hidden state [u][b]
__device__ float g_D[G3H * B_SZ];          // GEMM result [6144][64]
__device__ unsigned g_count = 0, g_release = 0;

// ---------------- helpers ----------------
__device__ __forceinline__ unsigned pk_bf16(float x, float y, int ph) {
    __nv_bfloat16 hx = __float2bfloat16_rn(x);
    __nv_bfloat16 hy = __float2bfloat16_rn(y);
    if (ph) {
        hx = __float2bfloat16_rn(x - __bfloat162float(hx));
        hy = __float2bfloat16_rn(y - __bfloat162float(hy));
    }
    return ((unsigned)*(unsigned short*)&hy << 16) | *(unsigned short*)&hx;
}

#define MMAOP(d, A, B) \
    asm volatile("mma.sync.aligned.m16n8k16.row.col.f32.bf16.bf16.f32 " \
                 "{%0,%1,%2,%3}, {%4,%5,%6,%7}, {%8,%9}, {%0,%1,%2,%3};" \
                 : "+f"((d)[0]), "+f"((d)[1]), "+f"((d)[2]), "+f"((d)[3]) \
                 : "r"((A).x), "r"((A).y), "r"((A).z), "r"((A).w), \
                   "r"((B).x), "r"((B).y))

// ---------------- init kernels ----------------
// W fragments: task per (ph, mt, kt, lane)
__global__ void w_init(const float* __restrict__ whh) {
    int id = blockIdx.x * 256 + threadIdx.x;   // 2*384*128*32 = 3,145,728
    int lane = id & 31;  id >>= 5;
    int kt   = id & 127; id >>= 7;
    int mt   = id % MT_TOT;
    int ph   = id / MT_TOT;
    int r0 = mt * 16 + (lane >> 2);
    int k0 = kt * 16 + (lane & 3) * 2;
    float2 a0 = *(const float2*)&whh[(size_t)r0 * H_SZ + k0];
    float2 a1 = *(const float2*)&whh[(size_t)(r0 + 8) * H_SZ + k0];
    float2 a2 = *(const float2*)&whh[(size_t)r0 * H_SZ + k0 + 8];
    float2 a3 = *(const float2*)&whh[(size_t)(r0 + 8) * H_SZ + k0 + 8];
    uint4 v;
    v.x = pk_bf16(a0.x, a0.y, ph);
    v.y = pk_bf16(a1.x, a1.y, ph);
    v.z = pk_bf16(a2.x, a2.y, ph);
    v.w = pk_bf16(a3.x, a3.y, ph);
    g_w[(((size_t)ph * MT_TOT + mt) * KT_N + kt) * 32 + lane] = v;
}

// h fragments + fp32 copy
__global__ void h_init(const float* __restrict__ h0) {
    int id = blockIdx.x * 256 + threadIdx.x;   // 65536
    int lane = id & 31;  id >>= 5;
    int kt   = id & 127; id >>= 7;
    int nt   = id & 7;
    int ph   = id >> 3;
    int b  = nt * 8 + (lane >> 2);
    int k0 = kt * 16 + (lane & 3) * 2;
    float2 h01 = *(const float2*)&h0[(size_t)b * H_SZ + k0];
    float2 h89 = *(const float2*)&h0[(size_t)b * H_SZ + k0 + 8];
    uint2 v;
    v.x = pk_bf16(h01.x, h01.y, ph);
    v.y = pk_bf16(h89.x, h89.y, ph);
    g_h[(((size_t)ph * 8 + nt) * KT_N + kt) * 32 + lane] = v;
}
__global__ void hf_init(const float* __restrict__ h0) {
    int id = blockIdx.x * 256 + threadIdx.x;   // 131072
    int u = id >> 6, b = id & 63;
    g_hf[id] = h0[(size_t)b * H_SZ + u];
}

// ---------------- main persistent kernel ----------------
__global__ void __launch_bounds__(NTH, 1)
gru_main(const float* __restrict__ inp,     // [T,B,3]
         const float* __restrict__ wih,     // [3H,3]
         const float* __restrict__ bias,    // [3H]
         const float* __restrict__ bias_n,  // [H]
         float* __restrict__ out)           // [T,B]
{
    const int tid  = threadIdx.x;
    const int wid  = tid >> 5;
    const int lane = tid & 31;
    const int m    = blockIdx.x;
    const int mw   = wid % 3;          // balanced: each SMSP gets one warp of each mw
    const int nw   = wid / 3;          // 0..3
    const int mt   = m * 3 + mw;
    const int nt0  = nw * 2;

    unsigned rel_base = 0;
    if (tid == 0) rel_base = atomicAdd(&g_release, 0u);
    __syncthreads();

    // fragment base addresses (bytes), advance per kt by 512 (A) / 256 (B)
    const char* wB = (const char*)g_w;
    const char* hB = (const char*)g_h;
    const size_t aH  = ((size_t)mt * KT_N) * 512 + (size_t)lane * 16;
    const size_t aL  = ((size_t)(MT_TOT + mt) * KT_N) * 512 + (size_t)lane * 16;
    const size_t bh0 = ((size_t)nt0 * KT_N) * 256 + (size_t)lane * 8;
    const size_t bh1 = ((size_t)(nt0 + 1) * KT_N) * 256 + (size_t)lane * 8;
    const size_t bl0 = ((size_t)(8 + nt0) * KT_N) * 256 + (size_t)lane * 8;
    const size_t bl1 = ((size_t)(8 + nt0 + 1) * KT_N) * 256 + (size_t)lane * 8;

    for (int t = 0; t < T_STEPS; t++) {
        float acc0[4] = {0.f, 0.f, 0.f, 0.f};
        float acc1[4] = {0.f, 0.f, 0.f, 0.f};

        // ---------------- GEMM: no SMEM, no syncs; register prefetch pipeline ----------------
        uint4 Ah = *(const uint4*)(wB + aH);
        uint4 Al = *(const uint4*)(wB + aL);
        uint2 Bh0 = __ldcg((const uint2*)(hB + bh0));
        uint2 Bh1 = __ldcg((const uint2*)(hB + bh1));
        uint2 Bl0 = __ldcg((const uint2*)(hB + bl0));
        uint2 Bl1 = __ldcg((const uint2*)(hB + bl1));

        #pragma unroll 4
        for (int kt = 0; kt < KT_N; kt++) {
            uint4 nAh, nAl;
            uint2 nBh0, nBh1, nBl0, nBl1;
            if (kt + 1 < KT_N) {
                size_t oA = (size_t)(kt + 1) * 512;
                size_t oB = (size_t)(kt + 1) * 256;
                nAh  = *(const uint4*)(wB + aH + oA);
                nAl  = *(const uint4*)(wB + aL + oA);
                nBh0 = __ldcg((const uint2*)(hB + bh0 + oB));
                nBh1 = __ldcg((const uint2*)(hB + bh1 + oB));
                nBl0 = __ldcg((const uint2*)(hB + bl0 + oB));
                nBl1 = __ldcg((const uint2*)(hB + bl1 + oB));
            }
            MMAOP(acc0, Ah, Bh0);   // Whi * hhi
            MMAOP(acc1, Ah, Bh1);
            MMAOP(acc0, Ah, Bl0);   // Whi * hlo
            MMAOP(acc1, Ah, Bl1);
            MMAOP(acc0, Al, Bh0);   // Wlo * hhi
            MMAOP(acc1, Al, Bh1);
            Ah = nAh; Al = nAl;
            Bh0 = nBh0; Bh1 = nBh1; Bl0 = nBl0; Bl1 = nBl1;
        }

        // ---------------- epilogue: D frags -> g_D ----------------
        {
            int row0 = mt * 16 + (lane >> 2);
            int colb = (lane & 3) * 2;
            int c0 = nt0 * 8 + colb;
            int c1 = (nt0 + 1) * 8 + colb;
            *(float2*)&g_D[(size_t)row0 * B_SZ + c0]       = make_float2(acc0[0], acc0[1]);
            *(float2*)&g_D[(size_t)(row0 + 8) * B_SZ + c0] = make_float2(acc0[2], acc0[3]);
            *(float2*)&g_D[(size_t)row0 * B_SZ + c1]       = make_float2(acc1[0], acc1[1]);
            *(float2*)&g_D[(size_t)(row0 + 8) * B_SZ + c1] = make_float2(acc1[2], acc1[3]);
        }

        // ---- grid barrier #1 (D ready) ----
        __syncthreads();
        if (tid == 0) {
            __threadfence();
            unsigned prev = atomicAdd(&g_count, 1u);
            if (prev == NCTA - 1) { atomicExch(&g_count, 0u); __threadfence(); atomicAdd(&g_release, 1u); }
            else { unsigned tgt = rel_base + 2u * (unsigned)t + 1u;
                   while (atomicAdd(&g_release, 0u) < tgt) __nanosleep(32); }
            __threadfence();
        }
        __syncthreads();

        // ---------------- gate phase: CTA m owns u in [m*16, m*16+16) ----------------
        // thread (tid<256): b = tid&63, kg = tid>>6; computes 4 units, writes one B-frag word pair
        if (tid < 256) {
            const int b  = tid & 63;
            const int kg = tid >> 6;               // 0..3  (lane%4 within frag)
            const float* xt = inp + (size_t)t * (B_SZ * 3);
            const float x0 = xt[b * 3 + 0], x1 = xt[b * 3 + 1], x2 = xt[b * 3 + 2];
            float hn[4];
            #pragma unroll
            for (int i = 0; i < 4; i++) {
                int kk = kg * 2 + (i & 1) + (i >> 1) * 8;   // {2kg, 2kg+1, 2kg+8, 2kg+9}
                int u  = m * 16 + kk;
                float dr = __ldcg(&g_D[(size_t)u * B_SZ + b]);
                float dz = __ldcg(&g_D[(size_t)(H_SZ + u) * B_SZ + b]);
                float dn = __ldcg(&g_D[(size_t)(2 * H_SZ + u) * B_SZ + b]);
                float igr = bias[u]            + x0 * wih[u * 3]              + x1 * wih[u * 3 + 1]              + x2 * wih[u * 3 + 2];
                float igz = bias[H_SZ + u]     + x0 * wih[(H_SZ + u) * 3]     + x1 * wih[(H_SZ + u) * 3 + 1]     + x2 * wih[(H_SZ + u) * 3 + 2];
                float ign = bias[2 * H_SZ + u] + x0 * wih[(2 * H_SZ + u) * 3] + x1 * wih[(2 * H_SZ + u) * 3 + 1] + x2 * wih[(2 * H_SZ + u) * 3 + 2];
                float hold = g_hf[(size_t)u * B_SZ + b];
                float rg = 1.0f / (1.0f + expf(-(igr + dr)));
                float zg = 1.0f / (1.0f + expf(-(igz + dz)));
                float nn = tanhf(ign + rg * (dn + bias_n[u]));
                float h2 = nn + zg * (hold - nn);
                hn[i] = h2;
                g_hf[(size_t)u * B_SZ + b] = h2;
            }
            // write fragment words (kt for this CTA's u-range is exactly m)
            int nt    = b >> 3;
            int lane2 = (b & 7) * 4 + kg;
            size_t i0 = (((size_t)nt * KT_N) + m) * 32 + lane2;            // phase 0 (hi)
            size_t i1 = ((((size_t)8 + nt) * KT_N) + m) * 32 + lane2;      // phase 1 (lo)
            uint2 vhi, vlo;
            vhi.x = pk_bf16(hn[0], hn[1], 0);
            vhi.y = pk_bf16(hn[2], hn[3], 0);
            vlo.x = pk_bf16(hn[0], hn[1], 1);
            vlo.y = pk_bf16(hn[2], hn[3], 1);
            g_h[i0] = vhi;
            g_h[i1] = vlo;
            if (m == 0 && kg == 0) out[(size_t)t * B_SZ + b] = hn[0];  // u == 0
        }

        // ---- grid barrier #2 (h ready) ----
        __syncthreads();
        if (tid == 0) {
            __threadfence();
            unsigned prev = atomicAdd(&g_count, 1u);
            if (prev == NCTA - 1) { atomicExch(&g_count, 0u); __threadfence(); atomicAdd(&g_release, 1u); }
            else { unsigned tgt = rel_base + 2u * (unsigned)t + 2u;
                   while (atomicAdd(&g_release, 0u) < tgt) __nanosleep(32); }
            __threadfence();
        }
        __syncthreads();
    }
}

extern "C" void kernel_launch(void* const* d_in, const int* in_sizes, int n_in,
                              void* d_out, int out_size) {
    const float* inp  = (const float*)d_in[0];  // [T,B,3]
    const float* h0   = (const float*)d_in[1];  // [B,H]
    const float* wih  = (const float*)d_in[2];  // [3H,3]
    const float* whh  = (const float*)d_in[3];  // [3H,H]
    const float* bias = (const float*)d_in[4];  // [3H]
    const float* bn   = (const float*)d_in[5];  // [H]
    float* out = (float*)d_out;                 // [T,B]

    w_init<<<12288, 256>>>(whh);   // 3,145,728 tasks
    h_init<<<256, 256>>>(h0);      // 65,536 tasks
    hf_init<<<512, 256>>>(h0);     // 131,072 tasks
    gru_main<<<NCTA, NTH>>>(inp, wih, bias, bn, out);
}

// round 8
// speedup vs baseline: 3.7393x; 1.4656x over previous
#include <cuda_runtime.h>
#include <cuda_bf16.h>
#include <cstdint>
#include <math.h>

// ---------------- problem constants ----------------
#define T_STEPS 1024
#define B_SZ    64
#define H_SZ    2048
#define G3H     6144

// ---------------- kernel config ----------------
#define NCTA   128          // persistent CTAs; CTA m owns gate units [16m,16m+16)
#define NTH    384          // 12 warps = 3 (m: r/z/n gate rows) x 4 (k-split)
#define MT_TOT 384          // total m16 tiles
#define KT_N   128          // k16 tiles (2048/16)
#define KT_PW  32           // kt iterations per warp (KT_N/4)
#define COLP   66           // padded smem D row stride (floats)
#define SMEM_DYN (4 * 3 * 16 * COLP * 4)   // 50688 B

// ---------------- persistent device state (fragment-ordered images) ----------------
// W: [phase(hi/lo)][mt 384][kt 128][lane 32] x 16B  (A frag a0..a3 per lane)
__device__ uint4 g_w[(size_t)2 * MT_TOT * KT_N * 32];
// h: [parity 2][phase 2][nt 8][kt 128][lane 32] x 8B  (B frag b0,b1 per lane)
#define HBUF ((size_t)2 * 8 * KT_N * 32)
__device__ uint2 g_h[2 * HBUF];
__device__ float g_hf[H_SZ * B_SZ];        // exact fp32 hidden state [u][b]
__device__ unsigned g_count = 0, g_release = 0;

// ---------------- helpers ----------------
__device__ __forceinline__ unsigned pk_bf16(float x, float y, int ph) {
    __nv_bfloat16 hx = __float2bfloat16_rn(x);
    __nv_bfloat16 hy = __float2bfloat16_rn(y);
    if (ph) {
        hx = __float2bfloat16_rn(x - __bfloat162float(hx));
        hy = __float2bfloat16_rn(y - __bfloat162float(hy));
    }
    return ((unsigned)*(unsigned short*)&hy << 16) | *(unsigned short*)&hx;
}

#define MMAOP(d, A, B) \
    asm volatile("mma.sync.aligned.m16n8k16.row.col.f32.bf16.bf16.f32 " \
                 "{%0,%1,%2,%3}, {%4,%5,%6,%7}, {%8,%9}, {%0,%1,%2,%3};" \
                 : "+f"((d)[0]), "+f"((d)[1]), "+f"((d)[2]), "+f"((d)[3]) \
                 : "r"((A).x), "r"((A).y), "r"((A).z), "r"((A).w), \
                   "r"((B).x), "r"((B).y))

// ---------------- init kernels (fragment images) ----------------
__global__ void w_init(const float* __restrict__ whh) {
    int id = blockIdx.x * 256 + threadIdx.x;   // 2*384*128*32 = 3,145,728
    int lane = id & 31;  id >>= 5;
    int kt   = id & 127; id >>= 7;
    int mt   = id % MT_TOT;
    int ph   = id / MT_TOT;
    int r0 = mt * 16 + (lane >> 2);
    int k0 = kt * 16 + (lane & 3) * 2;
    float2 a0 = *(const float2*)&whh[(size_t)r0 * H_SZ + k0];
    float2 a1 = *(const float2*)&whh[(size_t)(r0 + 8) * H_SZ + k0];
    float2 a2 = *(const float2*)&whh[(size_t)r0 * H_SZ + k0 + 8];
    float2 a3 = *(const float2*)&whh[(size_t)(r0 + 8) * H_SZ + k0 + 8];
    uint4 v;
    v.x = pk_bf16(a0.x, a0.y, ph);
    v.y = pk_bf16(a1.x, a1.y, ph);
    v.z = pk_bf16(a2.x, a2.y, ph);
    v.w = pk_bf16(a3.x, a3.y, ph);
    g_w[(((size_t)ph * MT_TOT + mt) * KT_N + kt) * 32 + lane] = v;
}

__global__ void h_init(const float* __restrict__ h0) {
    int id = blockIdx.x * 256 + threadIdx.x;   // 65536 (parity-0 buffer)
    int lane = id & 31;  id >>= 5;
    int kt   = id & 127; id >>= 7;
    int nt   = id & 7;
    int ph   = id >> 3;
    int b  = nt * 8 + (lane >> 2);
    int k0 = kt * 16 + (lane & 3) * 2;
    float2 h01 = *(const float2*)&h0[(size_t)b * H_SZ + k0];
    float2 h89 = *(const float2*)&h0[(size_t)b * H_SZ + k0 + 8];
    uint2 v;
    v.x = pk_bf16(h01.x, h01.y, ph);
    v.y = pk_bf16(h89.x, h89.y, ph);
    g_h[(((size_t)ph * 8 + nt) * KT_N + kt) * 32 + lane] = v;
}
__global__ void hf_init(const float* __restrict__ h0) {
    int id = blockIdx.x * 256 + threadIdx.x;   // 131072
    int u = id >> 6, b = id & 63;
    g_hf[id] = h0[(size_t)b * H_SZ + u];
}

// ---------------- main persistent kernel ----------------
__global__ void __launch_bounds__(NTH, 1)
gru_main(const float* __restrict__ inp,     // [T,B,3]
         const float* __restrict__ wih,     // [3H,3]
         const float* __restrict__ bias,    // [3H]
         const float* __restrict__ bias_n,  // [H]
         float* __restrict__ out)           // [T,B]
{
    extern __shared__ float Dp[];           // [ks 4][gate 3][row 16][COLP]

    const int tid  = threadIdx.x;
    const int wid  = tid >> 5;
    const int lane = tid & 31;
    const int m    = blockIdx.x;
    const int mw   = wid % 3;          // gate: 0=r(u) 1=z(H+u) 2=n(2H+u); balanced on SMSPs
    const int ks   = wid / 3;          // k-split 0..3
    const int mt   = m + 128 * mw;     // CTA-local gate rows
    const int kt0  = ks * KT_PW;

    unsigned rel_base = 0;
    if (tid == 0) rel_base = atomicAdd(&g_release, 0u);
    __syncthreads();

    const uint4* pW  = g_w + (((size_t)mt) * KT_N + kt0) * 32 + lane;
    const uint4* pWl = pW + (size_t)MT_TOT * KT_N * 32;

    for (int t = 0; t < T_STEPS; t++) {
        float acc[8][4];
        #pragma unroll
        for (int nt = 0; nt < 8; nt++)
            #pragma unroll
            for (int j = 0; j < 4; j++) acc[nt][j] = 0.0f;

        const uint2* pH = g_h + (size_t)(t & 1) * HBUF + (size_t)kt0 * 32 + lane;

        // ------------- GEMM slice: all N, kt in [kt0, kt0+32) -------------
        uint4 Ah = pW[0], Al = pWl[0];
        uint2 Bh[8], Bl[8];
        #pragma unroll
        for (int nt = 0; nt < 8; nt++) {
            Bh[nt] = __ldcg(pH + (size_t)nt * KT_N * 32);
            Bl[nt] = __ldcg(pH + (size_t)(8 + nt) * KT_N * 32);
        }

        #pragma unroll 2
        for (int kt = 0; kt < KT_PW; kt++) {
            uint4 nAh, nAl;
            uint2 nBh[8], nBl[8];
            if (kt + 1 < KT_PW) {
                nAh = pW[(kt + 1) * 32];
                nAl = pWl[(kt + 1) * 32];
                #pragma unroll
                for (int nt = 0; nt < 8; nt++) {
                    nBh[nt] = __ldcg(pH + (kt + 1) * 32 + (size_t)nt * KT_N * 32);
                    nBl[nt] = __ldcg(pH + (kt + 1) * 32 + (size_t)(8 + nt) * KT_N * 32);
                }
            }
            #pragma unroll
            for (int nt = 0; nt < 8; nt++) {
                MMAOP(acc[nt], Ah, Bh[nt]);   // Whi*hhi
                MMAOP(acc[nt], Ah, Bl[nt]);   // Whi*hlo
                MMAOP(acc[nt], Al, Bh[nt]);   // Wlo*hhi
            }
            Ah = nAh; Al = nAl;
            #pragma unroll
            for (int nt = 0; nt < 8; nt++) { Bh[nt] = nBh[nt]; Bl[nt] = nBl[nt]; }
        }

        // ------------- partials -> smem -------------
        {
            int r0 = lane >> 2, c0 = (lane & 3) * 2;
            int rbase = (ks * 3 + mw) * 16;
            #pragma unroll
            for (int nt = 0; nt < 8; nt++) {
                *(float2*)&Dp[(rbase + r0) * COLP + nt * 8 + c0]     = make_float2(acc[nt][0], acc[nt][1]);
                *(float2*)&Dp[(rbase + r0 + 8) * COLP + nt * 8 + c0] = make_float2(acc[nt][2], acc[nt][3]);
            }
        }
        __syncthreads();

        // ------------- gate phase (CTA-local D, SMEM reduction) -------------
        if (tid < 256) {
            const int b  = tid & 63;
            const int kg = tid >> 6;               // 0..3
            const float* xt = inp + (size_t)t * (B_SZ * 3);
            const float x0 = xt[b * 3 + 0], x1 = xt[b * 3 + 1], x2 = xt[b * 3 + 2];
            float hn[4];
            #pragma unroll
            for (int i = 0; i < 4; i++) {
                int kk = kg * 2 + (i & 1) + (i >> 1) * 8;   // {2kg, 2kg+1, 2kg+8, 2kg+9}
                int u  = m * 16 + kk;
                float dsum[3];
                #pragma unroll
                for (int g = 0; g < 3; g++) {
                    float s = 0.0f;
                    #pragma unroll
                    for (int p = 0; p < 4; p++) s += Dp[((p * 3 + g) * 16 + kk) * COLP + b];
                    dsum[g] = s;
                }
                float igr = bias[u]            + x0 * wih[u * 3]              + x1 * wih[u * 3 + 1]              + x2 * wih[u * 3 + 2];
                float igz = bias[H_SZ + u]     + x0 * wih[(H_SZ + u) * 3]     + x1 * wih[(H_SZ + u) * 3 + 1]     + x2 * wih[(H_SZ + u) * 3 + 2];
                float ign = bias[2 * H_SZ + u] + x0 * wih[(2 * H_SZ + u) * 3] + x1 * wih[(2 * H_SZ + u) * 3 + 1] + x2 * wih[(2 * H_SZ + u) * 3 + 2];
                float hold = g_hf[(size_t)u * B_SZ + b];
                float rg = 1.0f / (1.0f + expf(-(igr + dsum[0])));
                float zg = 1.0f / (1.0f + expf(-(igz + dsum[1])));
                float nn = tanhf(ign + rg * (dsum[2] + bias_n[u]));
                float h2 = nn + zg * (hold - nn);
                hn[i] = h2;
                g_hf[(size_t)u * B_SZ + b] = h2;
            }
            // write h fragment words into parity (t+1) buffer; kt column for CTA m's units is m
            int nt    = b >> 3;
            int lane2 = (b & 7) * 4 + kg;
            size_t pb = (size_t)((t + 1) & 1) * HBUF;
            size_t i0 = pb + (((size_t)nt * KT_N) + m) * 32 + lane2;            // hi
            size_t i1 = pb + ((((size_t)8 + nt) * KT_N) + m) * 32 + lane2;      // lo
            uint2 vhi, vlo;
            vhi.x = pk_bf16(hn[0], hn[1], 0);
            vhi.y = pk_bf16(hn[2], hn[3], 0);
            vlo.x = pk_bf16(hn[0], hn[1], 1);
            vlo.y = pk_bf16(hn[2], hn[3], 1);
            g_h[i0] = vhi;
            g_h[i1] = vlo;
            if (m == 0 && kg == 0) out[(size_t)t * B_SZ + b] = hn[0];  // u == 0
        }

        // ------------- single grid barrier per step (h published) -------------
        __syncthreads();
        if (tid == 0) {
            __threadfence();
            unsigned prev = atomicAdd(&g_count, 1u);
            if (prev == NCTA - 1) { atomicExch(&g_count, 0u); __threadfence(); atomicAdd(&g_release, 1u); }
            else { unsigned tgt = rel_base + (unsigned)t + 1u;
                   while (atomicAdd(&g_release, 0u) < tgt) __nanosleep(32); }
            __threadfence();
        }
        __syncthreads();
    }
}

extern "C" void kernel_launch(void* const* d_in, const int* in_sizes, int n_in,
                              void* d_out, int out_size) {
    const float* inp  = (const float*)d_in[0];  // [T,B,3]
    const float* h0   = (const float*)d_in[1];  // [B,H]
    const float* wih  = (const float*)d_in[2];  // [3H,3]
    const float* whh  = (const float*)d_in[3];  // [3H,H]
    const float* bias = (const float*)d_in[4];  // [3H]
    const float* bn   = (const float*)d_in[5];  // [H]
    float* out = (float*)d_out;                 // [T,B]

    cudaFuncSetAttribute(gru_main, cudaFuncAttributeMaxDynamicSharedMemorySize, SMEM_DYN);

    w_init<<<12288, 256>>>(whh);   // 3,145,728 tasks
    h_init<<<256, 256>>>(h0);      // 65,536 tasks
    hf_init<<<512, 256>>>(h0);     // 131,072 tasks
    gru_main<<<NCTA, NTH, SMEM_DYN>>>(inp, wih, bias, bn, out);
}

// round 9
// speedup vs baseline: 4.0320x; 1.0783x over previous
#include <cuda_runtime.h>
#include <cuda_bf16.h>
#include <cstdint>
#include <math.h>

// ---------------- problem constants ----------------
#define T_STEPS 1024
#define B_SZ    64
#define H_SZ    2048
#define G3H     6144

// ---------------- kernel config ----------------
#define NCTA   128          // persistent CTAs; CTA m owns gate units [16m,16m+16)
#define NTH    384          // 12 warps = 3 (m: r/z/n gate rows) x 4 (k-split)
#define MT_TOT 384          // total m16 tiles
#define KT_N   128          // k16 tiles (2048/16)
#define KT_PW  32           // kt iterations per warp (KT_N/4)
#define COLP   66           // padded smem D row stride (floats)
#define SMEM_DYN (4 * 3 * 16 * COLP * 4)   // 50688 B

// ---------------- persistent device state (fragment-ordered images) ----------------
// W: [phase(hi/lo)][mt 384][kt 128][lane 32] x 16B  (A frag a0..a3 per lane) + 1-kt pad
__device__ uint4 g_w[(size_t)2 * MT_TOT * KT_N * 32 + 32];
// h: [parity 2][nt 8][kt 128][lane 32] x 16B  = (hi.b01, hi.b89, lo.b01, lo.b89) + 1-kt pad
#define HBUF ((size_t)8 * KT_N * 32)
__device__ uint4 g_h[2 * HBUF + 32];
__device__ float g_hf[H_SZ * B_SZ];        // exact fp32 hidden state [u][b]
__device__ unsigned g_count = 0, g_release = 0;

// ---------------- helpers ----------------
__device__ __forceinline__ unsigned pk_bf16(float x, float y, int ph) {
    __nv_bfloat16 hx = __float2bfloat16_rn(x);
    __nv_bfloat16 hy = __float2bfloat16_rn(y);
    if (ph) {
        hx = __float2bfloat16_rn(x - __bfloat162float(hx));
        hy = __float2bfloat16_rn(y - __bfloat162float(hy));
    }
    return ((unsigned)*(unsigned short*)&hy << 16) | *(unsigned short*)&hx;
}

#define MMAOP(d, A, bx, by) \
    asm volatile("mma.sync.aligned.m16n8k16.row.col.f32.bf16.bf16.f32 " \
                 "{%0,%1,%2,%3}, {%4,%5,%6,%7}, {%8,%9}, {%0,%1,%2,%3};" \
                 : "+f"((d)[0]), "+f"((d)[1]), "+f"((d)[2]), "+f"((d)[3]) \
                 : "r"((A).x), "r"((A).y), "r"((A).z), "r"((A).w), \
                   "r"(bx), "r"(by))

// ---------------- init kernels (fragment images) ----------------
__global__ void w_init(const float* __restrict__ whh) {
    int id = blockIdx.x * 256 + threadIdx.x;   // 2*384*128*32 = 3,145,728
    int lane = id & 31;  id >>= 5;
    int kt   = id & 127; id >>= 7;
    int mt   = id % MT_TOT;
    int ph   = id / MT_TOT;
    int r0 = mt * 16 + (lane >> 2);
    int k0 = kt * 16 + (lane & 3) * 2;
    float2 a0 = *(const float2*)&whh[(size_t)r0 * H_SZ + k0];
    float2 a1 = *(const float2*)&whh[(size_t)(r0 + 8) * H_SZ + k0];
    float2 a2 = *(const float2*)&whh[(size_t)r0 * H_SZ + k0 + 8];
    float2 a3 = *(const float2*)&whh[(size_t)(r0 + 8) * H_SZ + k0 + 8];
    uint4 v;
    v.x = pk_bf16(a0.x, a0.y, ph);
    v.y = pk_bf16(a1.x, a1.y, ph);
    v.z = pk_bf16(a2.x, a2.y, ph);
    v.w = pk_bf16(a3.x, a3.y, ph);
    g_w[(((size_t)ph * MT_TOT + mt) * KT_N + kt) * 32 + lane] = v;
}

__global__ void h_init(const float* __restrict__ h0) {
    int id = blockIdx.x * 256 + threadIdx.x;   // 32768 (parity-0 buffer)
    int lane = id & 31;  id >>= 5;
    int kt   = id & 127; id >>= 7;
    int nt   = id & 7;
    int b  = nt * 8 + (lane >> 2);
    int k0 = kt * 16 + (lane & 3) * 2;
    float2 h01 = *(const float2*)&h0[(size_t)b * H_SZ + k0];
    float2 h89 = *(const float2*)&h0[(size_t)b * H_SZ + k0 + 8];
    uint4 v;
    v.x = pk_bf16(h01.x, h01.y, 0);
    v.y = pk_bf16(h89.x, h89.y, 0);
    v.z = pk_bf16(h01.x, h01.y, 1);
    v.w = pk_bf16(h89.x, h89.y, 1);
    g_h[(((size_t)nt * KT_N) + kt) * 32 + lane] = v;
}
__global__ void hf_init(const float* __restrict__ h0) {
    int id = blockIdx.x * 256 + threadIdx.x;   // 131072
    int u = id >> 6, b = id & 63;
    g_hf[id] = h0[(size_t)b * H_SZ + u];
}

// ---------------- main persistent kernel ----------------
__global__ void __launch_bounds__(NTH, 1)
gru_main(const float* __restrict__ inp,     // [T,B,3]
         const float* __restrict__ wih,     // [3H,3]
         const float* __restrict__ bias,    // [3H]
         const float* __restrict__ bias_n,  // [H]
         float* __restrict__ out)           // [T,B]
{
    extern __shared__ float Dp[];           // [ks 4][gate 3][row 16][COLP]

    const int tid  = threadIdx.x;
    const int wid  = tid >> 5;
    const int lane = tid & 31;
    const int m    = blockIdx.x;
    const int mw   = wid % 3;          // gate: 0=r(u) 1=z(H+u) 2=n(2H+u)
    const int ks   = wid / 3;          // k-split 0..3
    const int mt   = m + 128 * mw;     // CTA-local gate rows
    const int kt0  = ks * KT_PW;

    unsigned rel_base = 0;
    if (tid == 0) rel_base = atomicAdd(&g_release, 0u);
    __syncthreads();

    const uint4* pW  = g_w + (((size_t)mt) * KT_N + kt0) * 32 + lane;
    const uint4* pWl = pW + (size_t)MT_TOT * KT_N * 32;

    for (int t = 0; t < T_STEPS; t++) {
        float acc[8][4];
        #pragma unroll
        for (int nt = 0; nt < 8; nt++)
            #pragma unroll
            for (int j = 0; j < 4; j++) acc[nt][j] = 0.0f;

        // NOTE: B loads are plain LDG (L1-cached). Safe because the grid
        // barrier's gpu-scope __threadfence() emits CCTL.IVALL (L1 invalidate)
        // every step, so no stale h lines can survive across the barrier.
        const uint4* pH = g_h + (size_t)(t & 1) * HBUF + (size_t)kt0 * 32 + lane;

        // ------------- GEMM slice: all N, kt in [kt0, kt0+32) -------------
        uint4 Ah = pW[0], Al = pWl[0];
        uint4 Bv[8];
        #pragma unroll
        for (int nt = 0; nt < 8; nt++) Bv[nt] = pH[(size_t)nt * KT_N * 32];

        #pragma unroll 2
        for (int kt = 0; kt < KT_PW; kt++) {
            // unconditional prefetch (arrays padded by one kt column)
            uint4 nAh = pW[(kt + 1) * 32];
            uint4 nAl = pWl[(kt + 1) * 32];
            uint4 nBv[8];
            #pragma unroll
            for (int nt = 0; nt < 8; nt++)
                nBv[nt] = pH[(kt + 1) * 32 + (size_t)nt * KT_N * 32];

            #pragma unroll
            for (int nt = 0; nt < 8; nt++) {
                MMAOP(acc[nt], Ah, Bv[nt].x, Bv[nt].y);   // Whi*hhi
                MMAOP(acc[nt], Ah, Bv[nt].z, Bv[nt].w);   // Whi*hlo
                MMAOP(acc[nt], Al, Bv[nt].x, Bv[nt].y);   // Wlo*hhi
            }
            Ah = nAh; Al = nAl;
            #pragma unroll
            for (int nt = 0; nt < 8; nt++) Bv[nt] = nBv[nt];
        }

        // ------------- partials -> smem -------------
        {
            int r0 = lane >> 2, c0 = (lane & 3) * 2;
            int rbase = (ks * 3 + mw) * 16;
            #pragma unroll
            for (int nt = 0; nt < 8; nt++) {
                *(float2*)&Dp[(rbase + r0) * COLP + nt * 8 + c0]     = make_float2(acc[nt][0], acc[nt][1]);
                *(float2*)&Dp[(rbase + r0 + 8) * COLP + nt * 8 + c0] = make_float2(acc[nt][2], acc[nt][3]);
            }
        }
        __syncthreads();

        // ------------- gate phase (CTA-local D, SMEM reduction) -------------
        if (tid < 256) {
            const int b  = tid & 63;
            const int kg = tid >> 6;               // 0..3
            const float* xt = inp + (size_t)t * (B_SZ * 3);
            const float x0 = xt[b * 3 + 0], x1 = xt[b * 3 + 1], x2 = xt[b * 3 + 2];
            float hn[4];
            #pragma unroll
            for (int i = 0; i < 4; i++) {
                int kk = kg * 2 + (i & 1) + (i >> 1) * 8;   // {2kg, 2kg+1, 2kg+8, 2kg+9}
                int u  = m * 16 + kk;
                float dsum[3];
                #pragma unroll
                for (int g = 0; g < 3; g++) {
                    float s = 0.0f;
                    #pragma unroll
                    for (int p = 0; p < 4; p++) s += Dp[((p * 3 + g) * 16 + kk) * COLP + b];
                    dsum[g] = s;
                }
                float igr = bias[u]            + x0 * wih[u * 3]              + x1 * wih[u * 3 + 1]              + x2 * wih[u * 3 + 2];
                float igz = bias[H_SZ + u]     + x0 * wih[(H_SZ + u) * 3]     + x1 * wih[(H_SZ + u) * 3 + 1]     + x2 * wih[(H_SZ + u) * 3 + 2];
                float ign = bias[2 * H_SZ + u] + x0 * wih[(2 * H_SZ + u) * 3] + x1 * wih[(2 * H_SZ + u) * 3 + 1] + x2 * wih[(2 * H_SZ + u) * 3 + 2];
                float hold = g_hf[(size_t)u * B_SZ + b];
                float rg = 1.0f / (1.0f + expf(-(igr + dsum[0])));
                float zg = 1.0f / (1.0f + expf(-(igz + dsum[1])));
                float nn = tanhf(ign + rg * (dsum[2] + bias_n[u]));
                float h2 = nn + zg * (hold - nn);
                hn[i] = h2;
                g_hf[(size_t)u * B_SZ + b] = h2;
            }
            // write h fragment uint4 (hi+lo) into parity (t+1) buffer; kt column = m
            int nt    = b >> 3;
            int lane2 = (b & 7) * 4 + kg;
            uint4 v;
            v.x = pk_bf16(hn[0], hn[1], 0);
            v.y = pk_bf16(hn[2], hn[3], 0);
            v.z = pk_bf16(hn[0], hn[1], 1);
            v.w = pk_bf16(hn[2], hn[3], 1);
            g_h[(size_t)((t + 1) & 1) * HBUF + (((size_t)nt * KT_N) + m) * 32 + lane2] = v;
            if (m == 0 && kg == 0) out[(size_t)t * B_SZ + b] = hn[0];  // u == 0
        }

        // ------------- single grid barrier per step (h published + L1 IVALL) -------------
        __syncthreads();
        if (tid == 0) {
            __threadfence();
            unsigned prev = atomicAdd(&g_count, 1u);
            if (prev == NCTA - 1) { atomicExch(&g_count, 0u); __threadfence(); atomicAdd(&g_release, 1u); }
            else { unsigned tgt = rel_base + (unsigned)t + 1u;
                   while (atomicAdd(&g_release, 0u) < tgt) __nanosleep(32); }
            __threadfence();   // gpu-scope fence: orders + invalidates L1 (CCTL.IVALL)
        }
        __syncthreads();
    }
}

extern "C" void kernel_launch(void* const* d_in, const int* in_sizes, int n_in,
                              void* d_out, int out_size) {
    const float* inp  = (const float*)d_in[0];  // [T,B,3]
    const float* h0   = (const float*)d_in[1];  // [B,H]
    const float* wih  = (const float*)d_in[2];  // [3H,3]
    const float* whh  = (const float*)d_in[3];  // [3H,H]
    const float* bias = (const float*)d_in[4];  // [3H]
    const float* bn   = (const float*)d_in[5];  // [H]
    float* out = (float*)d_out;                 // [T,B]

    cudaFuncSetAttribute(gru_main, cudaFuncAttributeMaxDynamicSharedMemorySize, SMEM_DYN);

    w_init<<<12288, 256>>>(whh);   // 3,145,728 tasks
    h_init<<<128, 256>>>(h0);      // 32,768 tasks
    hf_init<<<512, 256>>>(h0);     // 131,072 tasks
    gru_main<<<NCTA, NTH, SMEM_DYN>>>(inp, wih, bias, bn, out);
}

// round 14
// speedup vs baseline: 4.1364x; 1.0259x over previous
#include <cuda_runtime.h>
#include <cuda_bf16.h>
#include <cstdint>
#include <math.h>

// ---------------- problem constants ----------------
#define T_STEPS 1024
#define B_SZ    64
#define H_SZ    2048
#define G3H     6144

// ---------------- kernel config ----------------
#define NCTA   128          // persistent CTAs; CTA m owns gate units [16m,16m+16)
#define NTH    384          // 12 warps = 3 (m: r/z/n gate rows) x 4 (k-split)
#define MT_TOT 384          // total m16 tiles
#define KT_N   128          // k16 tiles (2048/16)
#define KT_PW  32           // kt iterations per warp (KT_N/4)
#define COLP   66           // padded smem D row stride (floats)

// persistent smem layout (floats)
#define SM_DP   0                       // [ks4][gate3][row16][COLP]  = 12672
#define SM_HF   (4*3*16*COLP)           // 12672 : fp32 h_old [16][64]
#define SM_GC   (SM_HF + 1024)          // 13696 : gate coefs [16 units][3 gates][4]
#define SM_BN   (SM_GC + 192)           // 13888 : bias_n [16]
#define SMEM_DYN ((SM_BN + 16) * 4)     // 55616 B

// ---------------- persistent device state (fragment-ordered images) ----------------
// W: [phase(hi/lo)][mt 384][kt 128][lane 32] x 16B  (+1-kt pad)
__device__ uint4 g_w[(size_t)2 * MT_TOT * KT_N * 32 + 32];
// h: [parity 2][nt 8][kt 128][lane 32] x 16B = (hi.b01, hi.b89, lo.b01, lo.b89)  (+1-kt pad)
#define HBUF ((size_t)8 * KT_N * 32)
__device__ uint4 g_h[2 * HBUF + 32];
__device__ unsigned g_count = 0, g_release = 0;

// ---------------- helpers ----------------
__device__ __forceinline__ unsigned pk_bf16(float x, float y, int ph) {
    __nv_bfloat16 hx = __float2bfloat16_rn(x);
    __nv_bfloat16 hy = __float2bfloat16_rn(y);
    if (ph) {
        hx = __float2bfloat16_rn(x - __bfloat162float(hx));
        hy = __float2bfloat16_rn(y - __bfloat162float(hy));
    }
    return ((unsigned)*(unsigned short*)&hy << 16) | *(unsigned short*)&hx;
}

#define MMAOP(d, A, bx, by) \
    asm volatile("mma.sync.aligned.m16n8k16.row.col.f32.bf16.bf16.f32 " \
                 "{%0,%1,%2,%3}, {%4,%5,%6,%7}, {%8,%9}, {%0,%1,%2,%3};" \
                 : "+f"((d)[0]), "+f"((d)[1]), "+f"((d)[2]), "+f"((d)[3]) \
                 : "r"((A).x), "r"((A).y), "r"((A).z), "r"((A).w), \
                   "r"(bx), "r"(by))

// ---------------- init kernels (fragment images) ----------------
__global__ void w_init(const float* __restrict__ whh) {
    int id = blockIdx.x * 256 + threadIdx.x;   // 2*384*128*32 = 3,145,728
    int lane = id & 31;  id >>= 5;
    int kt   = id & 127; id >>= 7;
    int mt   = id % MT_TOT;
    int ph   = id / MT_TOT;
    int r0 = mt * 16 + (lane >> 2);
    int k0 = kt * 16 + (lane & 3) * 2;
    float2 a0 = *(const float2*)&whh[(size_t)r0 * H_SZ + k0];
    float2 a1 = *(const float2*)&whh[(size_t)(r0 + 8) * H_SZ + k0];
    float2 a2 = *(const float2*)&whh[(size_t)r0 * H_SZ + k0 + 8];
    float2 a3 = *(const float2*)&whh[(size_t)(r0 + 8) * H_SZ + k0 + 8];
    uint4 v;
    v.x = pk_bf16(a0.x, a0.y, ph);
    v.y = pk_bf16(a1.x, a1.y, ph);
    v.z = pk_bf16(a2.x, a2.y, ph);
    v.w = pk_bf16(a3.x, a3.y, ph);
    g_w[(((size_t)ph * MT_TOT + mt) * KT_N + kt) * 32 + lane] = v;
}

__global__ void h_init(const float* __restrict__ h0) {
    int id = blockIdx.x * 256 + threadIdx.x;   // 32768 (parity-0 buffer)
    int lane = id & 31;  id >>= 5;
    int kt   = id & 127; id >>= 7;
    int nt   = id & 7;
    int b  = nt * 8 + (lane >> 2);
    int k0 = kt * 16 + (lane & 3) * 2;
    float2 h01 = *(const float2*)&h0[(size_t)b * H_SZ + k0];
    float2 h89 = *(const float2*)&h0[(size_t)b * H_SZ + k0 + 8];
    uint4 v;
    v.x = pk_bf16(h01.x, h01.y, 0);
    v.y = pk_bf16(h89.x, h89.y, 0);
    v.z = pk_bf16(h01.x, h01.y, 1);
    v.w = pk_bf16(h89.x, h89.y, 1);
    g_h[(((size_t)nt * KT_N) + kt) * 32 + lane] = v;
}

// ---------------- main persistent kernel ----------------
__global__ void __launch_bounds__(NTH, 1)
gru_main(const float* __restrict__ inp,     // [T,B,3]
         const float* __restrict__ h0,      // [B,H]
         const float* __restrict__ wih,     // [3H,3]
         const float* __restrict__ bias,    // [3H]
         const float* __restrict__ bias_n,  // [H]
         float* __restrict__ out)           // [T,B]
{
    extern __shared__ float smf[];

    const int tid  = threadIdx.x;
    const int wid  = tid >> 5;
    const int lane = tid & 31;
    const int m    = blockIdx.x;
    const int mw   = wid % 3;          // gate: 0=r(u) 1=z(H+u) 2=n(2H+u)
    const int ks   = wid / 3;          // k-split 0..3
    const int mt   = m + 128 * mw;     // CTA-local gate rows
    const int kt0  = ks * KT_PW;

    unsigned rel_base = 0;
    if (tid == 0) rel_base = atomicAdd(&g_release, 0u);

    // ---- one-time CTA-resident state: h_old, gate coefs, bias_n -> persistent smem ----
    for (int idx = tid; idx < 16 * 64; idx += NTH) {
        int kk = idx >> 6, b = idx & 63;
        smf[SM_HF + idx] = h0[(size_t)b * H_SZ + m * 16 + kk];
    }
    for (int idx = tid; idx < 192; idx += NTH) {
        int u  = m * 16 + idx / 12;
        int g  = (idx % 12) >> 2;
        int cf = idx & 3;
        int grow = g * H_SZ + u;
        smf[SM_GC + idx] = (cf < 3) ? wih[grow * 3 + cf] : bias[grow];
    }
    if (tid < 16) smf[SM_BN + tid] = bias_n[m * 16 + tid];
    __syncthreads();

    const uint4* pW  = g_w + (((size_t)mt) * KT_N + kt0) * 32 + lane;
    const uint4* pWl = pW + (size_t)MT_TOT * KT_N * 32;

    // kt0 A fragments are step-invariant: pin in registers forever
    const uint4 A0h = pW[0], A0l = pWl[0];

    for (int t = 0; t < T_STEPS; t++) {
        // prefetch this step's input projection operands (consumed after GEMM)
        float x0 = 0.f, x1 = 0.f, x2 = 0.f;
        if (tid < 256) {
            const float* xt = inp + (size_t)t * (B_SZ * 3) + (tid & 63) * 3;
            x0 = __ldg(xt); x1 = __ldg(xt + 1); x2 = __ldg(xt + 2);
        }

        float acc[8][4];
        #pragma unroll
        for (int nt = 0; nt < 8; nt++)
            #pragma unroll
            for (int j = 0; j < 4; j++) acc[nt][j] = 0.0f;

        // B loads are plain LDG (L1-cached); safe because the grid barrier's
        // gpu-scope __threadfence() IVALLs L1 every step.
        const uint4* pH = g_h + (size_t)(t & 1) * HBUF + (size_t)kt0 * 32 + lane;

        uint4 Ah = A0h, Al = A0l;
        uint4 Bv[8];
        #pragma unroll
        for (int nt = 0; nt < 8; nt++) Bv[nt] = pH[(size_t)nt * KT_N * 32];

        #pragma unroll 2
        for (int kt = 0; kt < KT_PW; kt++) {
            uint4 nAh = pW[(kt + 1) * 32];          // padded: unconditional
            uint4 nAl = pWl[(kt + 1) * 32];
            uint4 nBv[8];
            #pragma unroll
            for (int nt = 0; nt < 8; nt++)
                nBv[nt] = pH[(kt + 1) * 32 + (size_t)nt * KT_N * 32];

            #pragma unroll
            for (int nt = 0; nt < 8; nt++) {
                MMAOP(acc[nt], Ah, Bv[nt].x, Bv[nt].y);   // Whi*hhi
                MMAOP(acc[nt], Ah, Bv[nt].z, Bv[nt].w);   // Whi*hlo
                MMAOP(acc[nt], Al, Bv[nt].x, Bv[nt].y);   // Wlo*hhi
            }
            Ah = nAh; Al = nAl;
            #pragma unroll
            for (int nt = 0; nt < 8; nt++) Bv[nt] = nBv[nt];
        }

        // ------------- partials -> smem -------------
        {
            int r0 = lane >> 2, c0 = (lane & 3) * 2;
            int rbase = (ks * 3 + mw) * 16;
            #pragma unroll
            for (int nt = 0; nt < 8; nt++) {
                *(float2*)&smf[SM_DP + (rbase + r0) * COLP + nt * 8 + c0]     = make_float2(acc[nt][0], acc[nt][1]);
                *(float2*)&smf[SM_DP + (rbase + r0 + 8) * COLP + nt * 8 + c0] = make_float2(acc[nt][2], acc[nt][3]);
            }
        }
        __syncthreads();

        // ------------- gate phase (all operands SMEM-resident) -------------
        if (tid < 256) {
            const int b  = tid & 63;
            const int kg = tid >> 6;               // 0..3
            float hn[4];
            #pragma unroll
            for (int i = 0; i < 4; i++) {
                int kk = kg * 2 + (i & 1) + (i >> 1) * 8;   // {2kg, 2kg+1, 2kg+8, 2kg+9}
                float dsum[3];
                #pragma unroll
                for (int g = 0; g < 3; g++) {
                    float s = 0.0f;
                    #pragma unroll
                    for (int p = 0; p < 4; p++)
                        s += smf[SM_DP + ((p * 3 + g) * 16 + kk) * COLP + b];
                    dsum[g] = s;
                }
                const float* gc = &smf[SM_GC + kk * 12];
                float igr = gc[3]  + x0 * gc[0] + x1 * gc[1] + x2 * gc[2];
                float igz = gc[7]  + x0 * gc[4] + x1 * gc[5] + x2 * gc[6];
                float ign = gc[11] + x0 * gc[8] + x1 * gc[9] + x2 * gc[10];
                float hold = smf[SM_HF + kk * 64 + b];
                float rg = 1.0f / (1.0f + expf(-(igr + dsum[0])));
                float zg = 1.0f / (1.0f + expf(-(igz + dsum[1])));
                float nn = tanhf(ign + rg * (dsum[2] + smf[SM_BN + kk]));
                float h2 = nn + zg * (hold - nn);
                hn[i] = h2;
                smf[SM_HF + kk * 64 + b] = h2;
            }
            // publish h fragment uint4 (hi+lo) into parity (t+1) buffer; kt column = m
            int nt    = b >> 3;
            int lane2 = (b & 7) * 4 + kg;
            uint4 v;
            v.x = pk_bf16(hn[0], hn[1], 0);
            v.y = pk_bf16(hn[2], hn[3], 0);
            v.z = pk_bf16(hn[0], hn[1], 1);
            v.w = pk_bf16(hn[2], hn[3], 1);
            g_h[(size_t)((t + 1) & 1) * HBUF + (((size_t)nt * KT_N) + m) * 32 + lane2] = v;
            if (m == 0 && kg == 0) out[(size_t)t * B_SZ + b] = hn[0];  // u == 0
        }

        // ------------- single grid barrier per step (h published + L1 IVALL) -------------
        __syncthreads();
        if (tid == 0) {
            __threadfence();                       // publish h stores (release)
            unsigned prev = atomicAdd(&g_count, 1u);
            if (prev == NCTA - 1) { atomicExch(&g_count, 0u); __threadfence(); atomicAdd(&g_release, 1u); }
            else {
                unsigned tgt = rel_base + (unsigned)t + 1u;
                volatile unsigned* rp = &g_release;   // plain L2 read poll (no atomic-ALU serialization)
                while (*rp < tgt) { }
            }
            __threadfence();                       // acquire + CCTL.IVALL (L1 invalidate)
        }
        __syncthreads();
    }
}

extern "C" void kernel_launch(void* const* d_in, const int* in_sizes, int n_in,
                              void* d_out, int out_size) {
    const float* inp  = (const float*)d_in[0];  // [T,B,3]
    const float* h0   = (const float*)d_in[1];  // [B,H]
    const float* wih  = (const float*)d_in[2];  // [3H,3]
    const float* whh  = (const float*)d_in[3];  // [3H,H]
    const float* bias = (const float*)d_in[4];  // [3H]
    const float* bn   = (const float*)d_in[5];  // [H]
    float* out = (float*)d_out;                 // [T,B]

    cudaFuncSetAttribute(gru_main, cudaFuncAttributeMaxDynamicSharedMemorySize, SMEM_DYN);

    w_init<<<12288, 256>>>(whh);   // 3,145,728 tasks
    h_init<<<128, 256>>>(h0);      // 32,768 tasks
    gru_main<<<NCTA, NTH, SMEM_DYN>>>(inp, h0, wih, bias, bn, out);
}